// round 14
// baseline (speedup 1.0000x reference)
#include <cuda_runtime.h>
#include <cuda_bf16.h>
#include <math.h>

// Problem constants
#define B_SZ   64
#define T_ENC  1024
#define D_ENC  512
#define Q_DIM  1024
#define H_DIM  256
#define M_MIX  5
#define EPS    1e-5f

#define TSPLIT 16
#define T_CHUNK (T_ENC / TSPLIT)   // 64

#define KPARTS 16
#define K_SUB  (Q_DIM / KPARTS)    // 64
#define CCHUNK 16                  // cols per block in K1

// scratch (device globals, no allocation)
__device__ float g_ctx_partial[B_SZ * TSPLIT * D_ENC];     // 2 MB
__device__ float g_h_part[B_SZ * KPARTS * H_DIM];          // 1 MB
__device__ float g_params[B_SZ * 16];                      // w[5], mu[5], isig[5]
__device__ int   g_sem[B_SZ];                              // zero-init; self-resetting

__device__ __forceinline__ float stable_sigmoid(float z) {
    if (z >= 0.0f) {
        return 1.0f / (1.0f + expf(-z));
    } else {
        float e = expf(z);
        return e / (1.0f + e);
    }
}

__device__ __forceinline__ float softplus(float x) {
    return fmaxf(x, 0.0f) + log1pf(expf(-fabsf(x)));
}

// ---------------------------------------------------------------------------
// K1: partial h = att @ W1, smem-tiled, W1 read exactly once chip-wide.
// grid (KPARTS=16, H_DIM/CCHUNK=16) = 256 blocks, 256 threads.
// Block (kp, cc): W1 tile [64k x 16col] in smem, att tile [64b x 64k] in smem.
// Thread (c = tid&15, g = tid>>4): 4 batches (g*4..g*4+3), col cc*16+c.
// ---------------------------------------------------------------------------
__global__ __launch_bounds__(256) void mlp1_part_kernel(
    const float* __restrict__ att,   // [B, Q_DIM]
    const float* __restrict__ W1)    // [Q_DIM, H_DIM]
{
    const int kp = blockIdx.x;
    const int cc = blockIdx.y;
    const int tid = threadIdx.x;

    __shared__ float w1_s[K_SUB][CCHUNK];      // 4 KB
    __shared__ float att_s[B_SZ][K_SUB + 1];   // 16.25 KB, padded vs bank conflicts

    // load W1 tile: 64 rows x 16 cols, 4 elems/thread
    #pragma unroll
    for (int idx = tid; idx < K_SUB * CCHUNK; idx += 256) {
        int kk = idx >> 4;
        int c  = idx & 15;
        w1_s[kk][c] = W1[(size_t)(kp * K_SUB + kk) * H_DIM + cc * CCHUNK + c];
    }
    // load att tile: 64 batches x 64 k, float4 (16 float4 per batch)
    #pragma unroll
    for (int idx = tid; idx < B_SZ * (K_SUB / 4); idx += 256) {
        int b  = idx >> 4;
        int k4 = idx & 15;
        float4 v = reinterpret_cast<const float4*>(
            att + (size_t)b * Q_DIM + kp * K_SUB)[k4];
        att_s[b][k4 * 4 + 0] = v.x;
        att_s[b][k4 * 4 + 1] = v.y;
        att_s[b][k4 * 4 + 2] = v.z;
        att_s[b][k4 * 4 + 3] = v.w;
    }
    __syncthreads();

    const int c = tid & 15;
    const int g = tid >> 4;          // batch group 0..15
    const int b0 = g * 4;

    float a0 = 0.f, a1 = 0.f, a2 = 0.f, a3 = 0.f;
    #pragma unroll 8
    for (int kk = 0; kk < K_SUB; kk++) {
        float w = w1_s[kk][c];
        a0 = fmaf(att_s[b0 + 0][kk], w, a0);
        a1 = fmaf(att_s[b0 + 1][kk], w, a1);
        a2 = fmaf(att_s[b0 + 2][kk], w, a2);
        a3 = fmaf(att_s[b0 + 3][kk], w, a3);
    }

    // g_h_part layout: [b][kp][col]
    const int col = cc * CCHUNK + c;
    float* dst = g_h_part + (size_t)kp * H_DIM + col;
    dst[(size_t)(b0 + 0) * KPARTS * H_DIM] = a0;
    dst[(size_t)(b0 + 1) * KPARTS * H_DIM] = a1;
    dst[(size_t)(b0 + 2) * KPARTS * H_DIM] = a2;
    dst[(size_t)(b0 + 3) * KPARTS * H_DIM] = a3;
}

// ---------------------------------------------------------------------------
// K2: reduce k-partials (+b1, relu) -> W2 warp dots -> mixture transforms.
// grid = 64 (one per batch), 512 threads.
// ---------------------------------------------------------------------------
__global__ __launch_bounds__(512) void mol_params_kernel(
    const float* __restrict__ mu_prev,       // [B, M]
    const float* __restrict__ b1,            // [H_DIM]
    const float* __restrict__ W2,            // [H_DIM, 15]
    const float* __restrict__ b2)            // [15]
{
    const int b    = blockIdx.x;
    const int tid  = threadIdx.x;
    const int lane = tid & 31;
    const int wid  = tid >> 5;               // 0..15

    __shared__ float h_s[H_DIM];
    __shared__ float p_s[16];

    // phase A: reduce KPARTS partials, add bias, relu
    if (tid < H_DIM) {
        const float* src = g_h_part + (size_t)b * KPARTS * H_DIM + tid;
        float s = b1[tid];
        #pragma unroll
        for (int p = 0; p < KPARTS; p++)
            s += src[(size_t)p * H_DIM];
        h_s[tid] = fmaxf(s, 0.0f);
    }
    __syncthreads();

    // phase B: params = h @ W2 + b2 — warp wid owns output wid (wid < 15)
    if (wid < 3 * M_MIX) {
        float acc = 0.0f;
        #pragma unroll
        for (int i = 0; i < H_DIM / 32; i++) {
            int k = i * 32 + lane;
            acc = fmaf(h_s[k], W2[k * (3 * M_MIX) + wid], acc);
        }
        #pragma unroll
        for (int off = 16; off > 0; off >>= 1)
            acc += __shfl_down_sync(0xffffffffu, acc, off);
        if (lane == 0) p_s[wid] = acc + b2[wid];
    }
    __syncthreads();

    // phase C: mixture transforms -> g_params
    if (tid < M_MIX) {
        float mx = p_s[0];
        #pragma unroll
        for (int m = 1; m < M_MIX; m++) mx = fmaxf(mx, p_s[m]);
        float den = 0.0f;
        #pragma unroll
        for (int m = 0; m < M_MIX; m++) den += expf(p_s[m] - mx);
        float w = expf(p_s[tid] - mx) / den + EPS;

        float sigma = softplus(p_s[M_MIX + tid]) + EPS;
        float Delta = softplus(p_s[2 * M_MIX + tid]);
        float mu    = mu_prev[b * M_MIX + tid] + Delta;

        g_params[b * 16 + tid]      = w;
        g_params[b * 16 + 5 + tid]  = mu;
        g_params[b * 16 + 10 + tid] = 1.0f / sigma;
    }
}

// ---------------------------------------------------------------------------
// K3: fused alpha + streaming partial context + last-block reduction.
// grid (B, TSPLIT), 128 threads.
// ---------------------------------------------------------------------------
__global__ __launch_bounds__(128) void ctx_stream_kernel(
    const float* __restrict__ memory,        // [B, T, D]
    const unsigned char* __restrict__ mask,  // [B, T]
    float* __restrict__ alpha_out,           // [B, T]
    float* __restrict__ ctx)                 // [B, D]
{
    const int b   = blockIdx.x;
    const int ts  = blockIdx.y;
    const int tid = threadIdx.x;

    __shared__ float par_s[16];
    __shared__ float a_s[T_CHUNK];
    __shared__ int is_last_s;

    if (tid < 15) par_s[tid] = g_params[b * 16 + tid];
    __syncthreads();

    if (tid < T_CHUNK) {
        const int t = ts * T_CHUNK + tid;
        float j0 = (float)t + 0.5f;
        float j1 = (float)t + 1.5f;
        float F0 = 0.0f, F1 = 0.0f;
        #pragma unroll
        for (int m = 0; m < M_MIX; m++) {
            float w  = par_s[m];
            float mu = par_s[5 + m];
            float is = par_s[10 + m];
            float s0 = stable_sigmoid((mu - j0) * is);
            float s1 = stable_sigmoid((mu - j1) * is);
            F0 += w / (1.0f + s0);
            F1 += w / (1.0f + s1);
        }
        float a = F1 - F0;
        if (a == 0.0f) a = EPS;
        if (mask[(size_t)b * T_ENC + t]) a = 0.0f;
        alpha_out[(size_t)b * T_ENC + t] = a;
        a_s[tid] = a;
    }
    __syncthreads();

    const float4* mem4 = reinterpret_cast<const float4*>(
        memory + ((size_t)b * T_ENC + (size_t)ts * T_CHUNK) * D_ENC);

    float4 acc = make_float4(0.f, 0.f, 0.f, 0.f);
    #pragma unroll 8
    for (int t = 0; t < T_CHUNK; t++) {
        float a = a_s[t];
        float4 v = mem4[(size_t)t * 128 + tid];
        acc.x = fmaf(a, v.x, acc.x);
        acc.y = fmaf(a, v.y, acc.y);
        acc.z = fmaf(a, v.z, acc.z);
        acc.w = fmaf(a, v.w, acc.w);
    }

    float4* part4 = reinterpret_cast<float4*>(
        g_ctx_partial + ((size_t)(b * TSPLIT + ts)) * D_ENC);
    part4[tid] = acc;

    __threadfence();
    __syncthreads();
    if (tid == 0)
        is_last_s = (atomicAdd(&g_sem[b], 1) == TSPLIT - 1) ? 1 : 0;
    __syncthreads();

    if (is_last_s) {
        const float4* base = reinterpret_cast<const float4*>(
            g_ctx_partial + (size_t)b * TSPLIT * D_ENC);
        float4 s = make_float4(0.f, 0.f, 0.f, 0.f);
        #pragma unroll
        for (int p = 0; p < TSPLIT; p++) {
            float4 v = base[(size_t)p * (D_ENC / 4) + tid];
            s.x += v.x; s.y += v.y; s.z += v.z; s.w += v.w;
        }
        reinterpret_cast<float4*>(ctx + (size_t)b * D_ENC)[tid] = s;
        if (tid == 0) g_sem[b] = 0;   // reset for next graph replay
    }
}

// ---------------------------------------------------------------------------
// kernel_launch
// inputs: 0 att_rnn_h, 1 memory, 2 mask(bool), 3 mu_prev, 4 W1, 5 b1, 6 W2, 7 b2
// output: context [64*512] then alpha [64*1024]
// ---------------------------------------------------------------------------
extern "C" void kernel_launch(void* const* d_in, const int* in_sizes, int n_in,
                              void* d_out, int out_size) {
    const float*         att     = (const float*)d_in[0];
    const float*         memory  = (const float*)d_in[1];
    const unsigned char* mask    = (const unsigned char*)d_in[2];
    const float*         mu_prev = (const float*)d_in[3];
    const float*         W1      = (const float*)d_in[4];
    const float*         b1      = (const float*)d_in[5];
    const float*         W2      = (const float*)d_in[6];
    const float*         b2      = (const float*)d_in[7];

    float* ctx_out   = (float*)d_out;
    float* alpha_out = (float*)d_out + B_SZ * D_ENC;

    dim3 grid1(KPARTS, H_DIM / CCHUNK);   // (16, 16) = 256 blocks
    mlp1_part_kernel<<<grid1, 256>>>(att, W1);

    mol_params_kernel<<<B_SZ, 512>>>(mu_prev, b1, W2, b2);

    dim3 grid3(B_SZ, TSPLIT);
    ctx_stream_kernel<<<grid3, 128>>>(memory, mask, alpha_out, ctx_out);
}

// round 15
// speedup vs baseline: 1.0008x; 1.0008x over previous
#include <cuda_runtime.h>
#include <cuda_bf16.h>
#include <math.h>

// Problem constants
#define B_SZ   64
#define T_ENC  1024
#define D_ENC  512
#define Q_DIM  1024
#define H_DIM  256
#define M_MIX  5
#define EPS    1e-5f

#define TSPLIT 16
#define T_CHUNK (T_ENC / TSPLIT)   // 64

#define KPARTS 16
#define K_SUB  (Q_DIM / KPARTS)    // 64
#define CCHUNK 16                  // cols per block in K1

// scratch (device globals, no allocation)
__device__ float g_ctx_partial[B_SZ * TSPLIT * D_ENC];     // 2 MB
__device__ float g_h_part[B_SZ * KPARTS * H_DIM];          // 1 MB
__device__ float g_params[B_SZ * 16];                      // w[5], mu[5], isig[5]
__device__ int   g_sem[B_SZ];                              // zero-init; self-resetting

__device__ __forceinline__ float stable_sigmoid(float z) {
    if (z >= 0.0f) {
        return 1.0f / (1.0f + expf(-z));
    } else {
        float e = expf(z);
        return e / (1.0f + e);
    }
}

__device__ __forceinline__ float softplus(float x) {
    return fmaxf(x, 0.0f) + log1pf(expf(-fabsf(x)));
}

// ---------------------------------------------------------------------------
// K1: partial h = att @ W1, smem-tiled, W1 read exactly once chip-wide.
// grid (KPARTS=16, H_DIM/CCHUNK=16) = 256 blocks, 256 threads.
// Block (kp, cc): W1 tile [64k x 16col] in smem, att tile [64b x 64k] in smem.
// Thread (c = tid&15, g = tid>>4): 4 batches (g*4..g*4+3), col cc*16+c.
// ---------------------------------------------------------------------------
__global__ __launch_bounds__(256) void mlp1_part_kernel(
    const float* __restrict__ att,   // [B, Q_DIM]
    const float* __restrict__ W1)    // [Q_DIM, H_DIM]
{
    const int kp = blockIdx.x;
    const int cc = blockIdx.y;
    const int tid = threadIdx.x;

    __shared__ float w1_s[K_SUB][CCHUNK];      // 4 KB
    __shared__ float att_s[B_SZ][K_SUB + 1];   // 16.25 KB, padded vs bank conflicts

    // load W1 tile: 64 rows x 16 cols, 4 elems/thread
    #pragma unroll
    for (int idx = tid; idx < K_SUB * CCHUNK; idx += 256) {
        int kk = idx >> 4;
        int c  = idx & 15;
        w1_s[kk][c] = W1[(size_t)(kp * K_SUB + kk) * H_DIM + cc * CCHUNK + c];
    }
    // load att tile: 64 batches x 64 k, float4 (16 float4 per batch)
    #pragma unroll
    for (int idx = tid; idx < B_SZ * (K_SUB / 4); idx += 256) {
        int b  = idx >> 4;
        int k4 = idx & 15;
        float4 v = reinterpret_cast<const float4*>(
            att + (size_t)b * Q_DIM + kp * K_SUB)[k4];
        att_s[b][k4 * 4 + 0] = v.x;
        att_s[b][k4 * 4 + 1] = v.y;
        att_s[b][k4 * 4 + 2] = v.z;
        att_s[b][k4 * 4 + 3] = v.w;
    }
    __syncthreads();

    const int c = tid & 15;
    const int g = tid >> 4;          // batch group 0..15
    const int b0 = g * 4;

    float a0 = 0.f, a1 = 0.f, a2 = 0.f, a3 = 0.f;
    #pragma unroll 8
    for (int kk = 0; kk < K_SUB; kk++) {
        float w = w1_s[kk][c];
        a0 = fmaf(att_s[b0 + 0][kk], w, a0);
        a1 = fmaf(att_s[b0 + 1][kk], w, a1);
        a2 = fmaf(att_s[b0 + 2][kk], w, a2);
        a3 = fmaf(att_s[b0 + 3][kk], w, a3);
    }

    // g_h_part layout: [b][kp][col]
    const int col = cc * CCHUNK + c;
    float* dst = g_h_part + (size_t)kp * H_DIM + col;
    dst[(size_t)(b0 + 0) * KPARTS * H_DIM] = a0;
    dst[(size_t)(b0 + 1) * KPARTS * H_DIM] = a1;
    dst[(size_t)(b0 + 2) * KPARTS * H_DIM] = a2;
    dst[(size_t)(b0 + 3) * KPARTS * H_DIM] = a3;
}

// ---------------------------------------------------------------------------
// K2: reduce k-partials (+b1, relu) -> W2 warp dots -> mixture transforms.
// grid = 64 (one per batch), 512 threads.
// ---------------------------------------------------------------------------
__global__ __launch_bounds__(512) void mol_params_kernel(
    const float* __restrict__ mu_prev,       // [B, M]
    const float* __restrict__ b1,            // [H_DIM]
    const float* __restrict__ W2,            // [H_DIM, 15]
    const float* __restrict__ b2)            // [15]
{
    const int b    = blockIdx.x;
    const int tid  = threadIdx.x;
    const int lane = tid & 31;
    const int wid  = tid >> 5;               // 0..15

    __shared__ float h_s[H_DIM];
    __shared__ float p_s[16];

    // phase A: reduce KPARTS partials, add bias, relu
    if (tid < H_DIM) {
        const float* src = g_h_part + (size_t)b * KPARTS * H_DIM + tid;
        float s = b1[tid];
        #pragma unroll
        for (int p = 0; p < KPARTS; p++)
            s += src[(size_t)p * H_DIM];
        h_s[tid] = fmaxf(s, 0.0f);
    }
    __syncthreads();

    // phase B: params = h @ W2 + b2 — warp wid owns output wid (wid < 15)
    if (wid < 3 * M_MIX) {
        float acc = 0.0f;
        #pragma unroll
        for (int i = 0; i < H_DIM / 32; i++) {
            int k = i * 32 + lane;
            acc = fmaf(h_s[k], W2[k * (3 * M_MIX) + wid], acc);
        }
        #pragma unroll
        for (int off = 16; off > 0; off >>= 1)
            acc += __shfl_down_sync(0xffffffffu, acc, off);
        if (lane == 0) p_s[wid] = acc + b2[wid];
    }
    __syncthreads();

    // phase C: mixture transforms -> g_params
    if (tid < M_MIX) {
        float mx = p_s[0];
        #pragma unroll
        for (int m = 1; m < M_MIX; m++) mx = fmaxf(mx, p_s[m]);
        float den = 0.0f;
        #pragma unroll
        for (int m = 0; m < M_MIX; m++) den += expf(p_s[m] - mx);
        float w = expf(p_s[tid] - mx) / den + EPS;

        float sigma = softplus(p_s[M_MIX + tid]) + EPS;
        float Delta = softplus(p_s[2 * M_MIX + tid]);
        float mu    = mu_prev[b * M_MIX + tid] + Delta;

        g_params[b * 16 + tid]      = w;
        g_params[b * 16 + 5 + tid]  = mu;
        g_params[b * 16 + 10 + tid] = 1.0f / sigma;
    }
}

// ---------------------------------------------------------------------------
// K3: fused alpha + streaming partial context + last-block reduction.
// grid (B, TSPLIT), 128 threads.
// ---------------------------------------------------------------------------
__global__ __launch_bounds__(128) void ctx_stream_kernel(
    const float* __restrict__ memory,        // [B, T, D]
    const unsigned char* __restrict__ mask,  // [B, T]
    float* __restrict__ alpha_out,           // [B, T]
    float* __restrict__ ctx)                 // [B, D]
{
    const int b   = blockIdx.x;
    const int ts  = blockIdx.y;
    const int tid = threadIdx.x;

    __shared__ float par_s[16];
    __shared__ float a_s[T_CHUNK];
    __shared__ int is_last_s;

    if (tid < 15) par_s[tid] = g_params[b * 16 + tid];
    __syncthreads();

    if (tid < T_CHUNK) {
        const int t = ts * T_CHUNK + tid;
        float j0 = (float)t + 0.5f;
        float j1 = (float)t + 1.5f;
        float F0 = 0.0f, F1 = 0.0f;
        #pragma unroll
        for (int m = 0; m < M_MIX; m++) {
            float w  = par_s[m];
            float mu = par_s[5 + m];
            float is = par_s[10 + m];
            float s0 = stable_sigmoid((mu - j0) * is);
            float s1 = stable_sigmoid((mu - j1) * is);
            F0 += w / (1.0f + s0);
            F1 += w / (1.0f + s1);
        }
        float a = F1 - F0;
        if (a == 0.0f) a = EPS;
        if (mask[(size_t)b * T_ENC + t]) a = 0.0f;
        alpha_out[(size_t)b * T_ENC + t] = a;
        a_s[tid] = a;
    }
    __syncthreads();

    const float4* mem4 = reinterpret_cast<const float4*>(
        memory + ((size_t)b * T_ENC + (size_t)ts * T_CHUNK) * D_ENC);

    float4 acc = make_float4(0.f, 0.f, 0.f, 0.f);
    #pragma unroll 8
    for (int t = 0; t < T_CHUNK; t++) {
        float a = a_s[t];
        float4 v = mem4[(size_t)t * 128 + tid];
        acc.x = fmaf(a, v.x, acc.x);
        acc.y = fmaf(a, v.y, acc.y);
        acc.z = fmaf(a, v.z, acc.z);
        acc.w = fmaf(a, v.w, acc.w);
    }

    float4* part4 = reinterpret_cast<float4*>(
        g_ctx_partial + ((size_t)(b * TSPLIT + ts)) * D_ENC);
    part4[tid] = acc;

    __threadfence();
    __syncthreads();
    if (tid == 0)
        is_last_s = (atomicAdd(&g_sem[b], 1) == TSPLIT - 1) ? 1 : 0;
    __syncthreads();

    if (is_last_s) {
        const float4* base = reinterpret_cast<const float4*>(
            g_ctx_partial + (size_t)b * TSPLIT * D_ENC);
        float4 s = make_float4(0.f, 0.f, 0.f, 0.f);
        #pragma unroll
        for (int p = 0; p < TSPLIT; p++) {
            float4 v = base[(size_t)p * (D_ENC / 4) + tid];
            s.x += v.x; s.y += v.y; s.z += v.z; s.w += v.w;
        }
        reinterpret_cast<float4*>(ctx + (size_t)b * D_ENC)[tid] = s;
        if (tid == 0) g_sem[b] = 0;   // reset for next graph replay
    }
}

// ---------------------------------------------------------------------------
// kernel_launch
// inputs: 0 att_rnn_h, 1 memory, 2 mask(bool), 3 mu_prev, 4 W1, 5 b1, 6 W2, 7 b2
// output: context [64*512] then alpha [64*1024]
// ---------------------------------------------------------------------------
extern "C" void kernel_launch(void* const* d_in, const int* in_sizes, int n_in,
                              void* d_out, int out_size) {
    const float*         att     = (const float*)d_in[0];
    const float*         memory  = (const float*)d_in[1];
    const unsigned char* mask    = (const unsigned char*)d_in[2];
    const float*         mu_prev = (const float*)d_in[3];
    const float*         W1      = (const float*)d_in[4];
    const float*         b1      = (const float*)d_in[5];
    const float*         W2      = (const float*)d_in[6];
    const float*         b2      = (const float*)d_in[7];

    float* ctx_out   = (float*)d_out;
    float* alpha_out = (float*)d_out + B_SZ * D_ENC;

    dim3 grid1(KPARTS, H_DIM / CCHUNK);   // (16, 16) = 256 blocks
    mlp1_part_kernel<<<grid1, 256>>>(att, W1);

    mol_params_kernel<<<B_SZ, 512>>>(mu_prev, b1, W2, b2);

    dim3 grid3(B_SZ, TSPLIT);
    ctx_stream_kernel<<<grid3, 128>>>(memory, mask, alpha_out, ctx_out);
}